// round 5
// baseline (speedup 1.0000x reference)
#include <cuda_runtime.h>
#include <math.h>

// Problem constants (fixed by the dataset)
#define N_NODES       65536
#define N_FEAT        64
#define N_HEADS       4
#define NTYPE         4
#define BATCH_ROWS    131072
#define ENTRIES_TOTAL (BATCH_ROWS * NTYPE)   // 524288
#define DEG           8                      // each node appears exactly 8 times
#define ALPHA         0.2f

typedef unsigned long long u64;

// Scratch (allocation-free rule: __device__ globals; zero-init at module load)
__device__ int  g_cnt[N_NODES];
__device__ int4 g_neigh4[N_NODES * DEG];   // per entry: (n0, n1, n2, pad)

// ---------------------------------------------------------------------------
// Kernel 1: for each batch row (x,y,z,w), emit 4 entries. The entry targeting
// the node at position i carries the other 3 ids IN ORDER (== cols[i] order,
// so neighbor slot k maps directly to att weight column k).
// g_cnt must be all-zero on entry (static zero-init; gat_kernel re-zeros).
// ---------------------------------------------------------------------------
__global__ void scatter_kernel(const int4* __restrict__ batch4) {
    int r = blockIdx.x * blockDim.x + threadIdx.x;
    if (r < BATCH_ROWS) {
        int4 b = batch4[r];
        int p;
        p = atomicAdd(&g_cnt[b.x], 1); g_neigh4[b.x * DEG + p] = make_int4(b.y, b.z, b.w, 0);
        p = atomicAdd(&g_cnt[b.y], 1); g_neigh4[b.y * DEG + p] = make_int4(b.x, b.z, b.w, 0);
        p = atomicAdd(&g_cnt[b.z], 1); g_neigh4[b.z * DEG + p] = make_int4(b.x, b.y, b.w, 0);
        p = atomicAdd(&g_cnt[b.w], 1); g_neigh4[b.w * DEG + p] = make_int4(b.x, b.y, b.z, 0);
    }
}

// ---------------------------------------------------------------------------
// Packed f32x2 helpers (FFMA2 — only reachable via PTX)
// ---------------------------------------------------------------------------
__device__ __forceinline__ u64 pack2(float lo, float hi) {
    u64 r; asm("mov.b64 %0, {%1, %2};" : "=l"(r) : "f"(lo), "f"(hi)); return r;
}
__device__ __forceinline__ u64 mul2(u64 a, u64 b) {
    u64 d; asm("mul.rn.f32x2 %0, %1, %2;" : "=l"(d) : "l"(a), "l"(b)); return d;
}
__device__ __forceinline__ void fma2(u64& d, u64 a, u64 b) {
    asm("fma.rn.f32x2 %0, %1, %2, %0;" : "+l"(d) : "l"(a), "l"(b));
}
__device__ __forceinline__ void unpack2(u64 v, float& lo, float& hi) {
    asm("mov.b64 {%0, %1}, %2;" : "=f"(lo), "=f"(hi) : "l"(v));
}

// ---------------------------------------------------------------------------
// Kernel 2: per-node reduction (atomic-free). WARP-PER-NODE mapping:
//   lane = fc (chunk 0..15)  +  16*hp (head-pair 0..1)
//   Lanes 0-15 and 16-31 issue identical gather addresses -> coalescer merges
//   them into the same L1 wavefronts, so L1 traffic is unchanged while
//   per-thread register state (acc, weights) is halved.
//   Each thread: 8 entries x 3 gathers, 2 heads x 4 feats accumulators,
//   out = leakyrelu(base + max-acc), 2 STG.128.
// ---------------------------------------------------------------------------
__global__ void __launch_bounds__(256, 4) gat_kernel(
    const float4* __restrict__ feat4,    // [N_NODES*16]
    const float*  __restrict__ attw,     // [4 heads][3 neighbor positions]
    float4*       __restrict__ out4)     // [N_NODES*64]
{
    int tid  = threadIdx.x;
    int t    = blockIdx.x * 8 + (tid >> 5);  // node (one warp per node)
    int lane = tid & 31;
    int fc   = lane & 15;                    // float4 chunk of the feature row
    int hp   = lane >> 4;                    // head pair: 0 -> heads 0,1 ; 1 -> heads 2,3

    // 6 weights for this thread's 2 heads, duplicated into packed f32x2 regs
    u64 wp[6];
#pragma unroll
    for (int k = 0; k < 6; k++) {
        float w = __ldg(attw + hp * 6 + k);
        wp[k] = pack2(w, w);
    }

    const float4 base = feat4[t * 16 + fc];

    // reset counter for next replay (this replay's entries already written)
    if (lane == 0) g_cnt[t] = 0;

    float acc[8];
#pragma unroll
    for (int k = 0; k < 8; k++) acc[k] = -INFINITY;

    const int4* np = g_neigh4 + t * DEG;

#pragma unroll
    for (int e = 0; e < 8; e++) {
        int4 ng = np[e];                      // warp-uniform broadcast load
        float4 F0 = feat4[ng.x * 16 + fc];
        float4 F1 = feat4[ng.y * 16 + fc];
        float4 F2 = feat4[ng.z * 16 + fc];

        u64 f0a = pack2(F0.x, F0.y), f0b = pack2(F0.z, F0.w);
        u64 f1a = pack2(F1.x, F1.y), f1b = pack2(F1.z, F1.w);
        u64 f2a = pack2(F2.x, F2.y), f2b = pack2(F2.z, F2.w);

#pragma unroll
        for (int a = 0; a < 2; a++) {         // local head index
            u64 mA = mul2(wp[a * 3 + 0], f0a);
            fma2(mA, wp[a * 3 + 1], f1a);
            fma2(mA, wp[a * 3 + 2], f2a);
            u64 mB = mul2(wp[a * 3 + 0], f0b);
            fma2(mB, wp[a * 3 + 1], f1b);
            fma2(mB, wp[a * 3 + 2], f2b);

            float a0, a1, a2, a3;
            unpack2(mA, a0, a1);
            unpack2(mB, a2, a3);
            acc[a * 4 + 0] = fmaxf(acc[a * 4 + 0], a0);
            acc[a * 4 + 1] = fmaxf(acc[a * 4 + 1], a1);
            acc[a * 4 + 2] = fmaxf(acc[a * 4 + 2], a2);
            acc[a * 4 + 3] = fmaxf(acc[a * 4 + 3], a3);
        }
    }

    // out[t, h*64 + f] with h = 2*hp + a  ->  float4 index t*64 + h*16 + fc
    int ob = t * 64 + hp * 32 + fc;
#pragma unroll
    for (int a = 0; a < 2; a++) {
        float x0 = base.x + acc[a * 4 + 0];
        float x1 = base.y + acc[a * 4 + 1];
        float x2 = base.z + acc[a * 4 + 2];
        float x3 = base.w + acc[a * 4 + 3];
        out4[ob + a * 16] = make_float4(fmaxf(x0, ALPHA * x0), fmaxf(x1, ALPHA * x1),
                                        fmaxf(x2, ALPHA * x2), fmaxf(x3, ALPHA * x3));
    }
}

// ---------------------------------------------------------------------------
// Launcher
// ---------------------------------------------------------------------------
extern "C" void kernel_launch(void* const* d_in, const int* in_sizes, int n_in,
                              void* d_out, int out_size) {
    const int*   batch = nullptr;
    const float* feat  = nullptr;
    const float* attw  = nullptr;
    for (int i = 0; i < n_in; i++) {
        if (in_sizes[i] == ENTRIES_TOTAL)              batch = (const int*)d_in[i];
        else if (in_sizes[i] == N_NODES * N_FEAT)      feat  = (const float*)d_in[i];
        else if (in_sizes[i] == N_HEADS * (NTYPE - 1)) attw  = (const float*)d_in[i];
    }

    scatter_kernel<<<(BATCH_ROWS + 255) / 256, 256>>>(
        reinterpret_cast<const int4*>(batch));
    gat_kernel<<<N_NODES / 8, 256>>>(
        reinterpret_cast<const float4*>(feat),
        attw,
        reinterpret_cast<float4*>(d_out));
}